// round 1
// baseline (speedup 1.0000x reference)
#include <cuda_runtime.h>

#define NEV 4000000
#define NB  8
#define HH  256
#define WW  256
#define NS  16

// ---------------- scratch (static __device__, allowed) ----------------
__device__ __align__(16) unsigned d_tmax[8];                 // per-batch max t (float bits)
__device__ __align__(16) int      d_container[NB*HH*WW];     // 2 MB
__device__ __align__(16) int      d_combiner[NB*NS*HH*WW];   // 32 MB
__device__ __align__(16) float    d_tsum[NB*(HH/2)*(WW/2)];  // 0.5 MB
__device__ __align__(16) int      d_cnt[NB*NS];
__device__ __align__(16) int      d_xsum[NB*NS];
__device__ __align__(16) int      d_ysum[NB*NS];
__device__ __align__(16) int      d_shift[NB*NS*2];          // [b][j] -> (sy, sx)

// ---------------- zero all scratch (graph-replay determinism) ----------------
__global__ void zero_all() {
    long long i = (long long)blockIdx.x * blockDim.x + threadIdx.x;
    const int4 z = make_int4(0, 0, 0, 0);
    if (i < 2097152) { ((int4*)d_combiner)[i]  = z; return; }  i -= 2097152;
    if (i <  131072) { ((int4*)d_container)[i] = z; return; }  i -=  131072;
    if (i <   32768) { ((int4*)d_tsum)[i]      = z; return; }  i -=   32768;
    if (i <      32) { ((int4*)d_cnt)[i]       = z; return; }  i -=      32;
    if (i <      32) { ((int4*)d_xsum)[i]      = z; return; }  i -=      32;
    if (i <      32) { ((int4*)d_ysum)[i]      = z; return; }  i -=      32;
    if (i <       2) { ((int4*)d_tmax)[i]      = z; return; }
}

// ---------------- pass 1: per-batch t-max + full-res count histogram ----------------
__global__ void k1_pass(const float* __restrict__ ev) {
    __shared__ unsigned smax[NB];
    int tid = threadIdx.x;
    if (tid < NB) smax[tid] = 0u;
    __syncthreads();

    int i = blockIdx.x * blockDim.x + tid;   // handles events 4i..4i+3
    if (i < NEV / 4) {
        const float4* p = (const float4*)ev + (size_t)i * 5;
        float4 r0 = p[0], r1 = p[1], r2 = p[2], r3 = p[3], r4 = p[4];
        float xs[4] = { r0.x, r1.y, r2.z, r3.w };
        float ys[4] = { r0.y, r1.z, r2.w, r4.x };
        float tv[4] = { r0.z, r1.w, r3.x, r4.y };
        float bv[4] = { r1.x, r2.y, r3.z, r4.w };
        #pragma unroll
        for (int e = 0; e < 4; e++) {
            int bi = (int)bv[e];
            atomicMax(&smax[bi], __float_as_uint(tv[e]));   // t > 0 -> bit order ok
            int xi = (int)xs[e], yi = (int)ys[e];
            atomicAdd(&d_container[(bi << 16) + (yi << 8) + xi], 1);
        }
    }
    __syncthreads();
    if (tid < NB) atomicMax(&d_tmax[tid], smax[tid]);
}

// ---------------- pass 2: combiner, timer, per-(b,ts) stats ----------------
__global__ void k2_pass(const float* __restrict__ ev) {
    __shared__ float stmax[NB];
    __shared__ int scnt[NB*NS], sxs[NB*NS], sys[NB*NS];
    int tid = threadIdx.x;
    if (tid < NB) stmax[tid] = __uint_as_float(d_tmax[tid]);
    for (int k = tid; k < NB*NS; k += blockDim.x) { scnt[k] = 0; sxs[k] = 0; sys[k] = 0; }
    __syncthreads();

    int i = blockIdx.x * blockDim.x + tid;
    if (i < NEV / 4) {
        const float4* p = (const float4*)ev + (size_t)i * 5;
        float4 r0 = p[0], r1 = p[1], r2 = p[2], r3 = p[3], r4 = p[4];
        float xs[4] = { r0.x, r1.y, r2.z, r3.w };
        float ys[4] = { r0.y, r1.z, r2.w, r4.x };
        float tv[4] = { r0.z, r1.w, r3.x, r4.y };
        float bv[4] = { r1.x, r2.y, r3.z, r4.w };
        #pragma unroll
        for (int e = 0; e < 4; e++) {
            int bi = (int)bv[e];
            int xi = (int)xs[e], yi = (int)ys[e];
            float tn = __fdiv_rn(tv[e], stmax[bi]);          // IEEE even under fast-math
            int ts = 0;
            #pragma unroll
            for (int k = 1; k < 16; k++) ts += (tn >= (float)k * 0.0625f);
            if (ts) atomicAdd(&d_combiner[(((bi << 4) + ts) << 16) + (yi << 8) + xi], ts);
            atomicAdd(&d_tsum[(bi << 14) + ((yi >> 1) << 7) + (xi >> 1)], tn);
            int bin = (bi << 4) + ts;
            atomicAdd(&scnt[bin], 1);
            atomicAdd(&sxs[bin], xi);
            atomicAdd(&sys[bin], yi);
        }
    }
    __syncthreads();
    for (int k = tid; k < NB*NS; k += blockDim.x) {
        if (scnt[k]) {
            atomicAdd(&d_cnt[k],  scnt[k]);
            atomicAdd(&d_xsum[k], sxs[k]);
            atomicAdd(&d_ysum[k], sys[k]);
        }
    }
}

// ---------------- pass 3: fold the sequential combine into per-slice total shifts ----------------
__global__ void k3_plan() {
    int b = threadIdx.x;
    if (b >= NB) return;
    float xm[NS], ym[NS];
    int   c[NS];
    for (int i = 0; i < NS; i++) {
        c[i] = d_cnt[b*NS + i];
        float cf = (float)c[i];
        xm[i] = __fdiv_rn((float)d_xsum[b*NS + i], cf);
        ym[i] = __fdiv_rn((float)d_ysum[b*NS + i], cf);
    }
    int Sy[NS], Sx[NS];
    for (int i = 0; i < NS; i++) { Sy[i] = 0; Sx[i] = 0; }
    float x_mean = xm[0], y_mean = ym[0];
    int pts = c[0];                      // NOTE: reference never updates pts
    for (int i = 1; i < NS; i++) {
        bool cond = c[i] > pts;
        float dxf = cond ? (xm[i] - x_mean) : (x_mean - xm[i]);
        float dyf = cond ? (ym[i] - y_mean) : (y_mean - ym[i]);
        int dx = (int)floorf(dxf);
        int dy = (int)floorf(dyf);
        int sx = dx > 0 ? dx : 0;
        int sy = dy > 0 ? dy : 0;
        if (cond) {
            // accumulated segment (slices 0..i-1) gets shifted; slice i joins unshifted
            for (int j = 0; j < i; j++) { Sy[j] += sy; Sx[j] += sx; }
            x_mean = xm[i];
            y_mean = ym[i];
        } else {
            Sy[i] = sy; Sx[i] = sx;      // slice i joins pre-shifted
        }
    }
    for (int j = 0; j < NS; j++) {
        d_shift[(b*NS + j)*2 + 0] = Sy[j];
        d_shift[(b*NS + j)*2 + 1] = Sx[j];
    }
}

// ---------------- pass 4: assemble all 5 output channels ----------------
__global__ void k4_out(float* __restrict__ out) {
    __shared__ int ssy[NS], ssx[NS];
    int idx = blockIdx.x * blockDim.x + threadIdx.x;  // 0..131071
    int b = idx >> 14;                                 // 16384 pixels per batch; 256 | 16384
    if (threadIdx.x < NS) {
        ssy[threadIdx.x] = d_shift[(b*NS + threadIdx.x)*2 + 0];
        ssx[threadIdx.x] = d_shift[(b*NS + threadIdx.x)*2 + 1];
    }
    __syncthreads();

    int rem = idx & 16383;
    int y2 = rem >> 7, x2 = rem & 127;
    int y = y2 << 1, x = x2 << 1;

    const int* cb = d_container + (b << 16);
    int c00 = cb[(y << 8) + x];
    int c01 = cb[(y << 8) + x + 1];
    int c10 = cb[((y + 1) << 8) + x];
    int c11 = cb[((y + 1) << 8) + x + 1];

    float dxv = (float)((c00 - c01) + (c10 - c11));
    float dyv = (float)((c00 - c10) + (c01 - c11));
    int   cnt4 = c00 + c01 + c10 + c11;               // == reference's half-res counter
    float counter = (float)cnt4;
    float divider = (cnt4 == 0) ? 1.0f : counter;
    float timer = d_tsum[idx] / divider;

    int acc = 0;
    #pragma unroll
    for (int j = 1; j < NS; j++) {                    // slice 0 is identically zero (adds ts=0)
        int yy = y - ssy[j];
        int xx = x - ssx[j];
        if (yy >= 0 && xx >= 0)
            acc += d_combiner[(((b << 4) + j) << 16) + (yy << 8) + xx];
    }
    float comb = fmaxf((float)acc - (float)NS, 0.0f);

    float* ob = out + ((size_t)b * 5 << 14);
    int pix = (y2 << 7) + x2;
    ob[0 * 16384 + pix] = dxv;
    ob[1 * 16384 + pix] = dyv;
    ob[2 * 16384 + pix] = timer;
    ob[3 * 16384 + pix] = counter;
    ob[4 * 16384 + pix] = comb;
}

// ---------------- launch ----------------
extern "C" void kernel_launch(void* const* d_in, const int* in_sizes, int n_in,
                              void* d_out, int out_size) {
    const float* ev = (const float*)d_in[0];

    zero_all<<<(2261090 + 255) / 256, 256>>>();
    int blocks = (NEV / 4 + 255) / 256;
    k1_pass<<<blocks, 256>>>(ev);
    k2_pass<<<blocks, 256>>>(ev);
    k3_plan<<<1, 32>>>();
    k4_out<<<131072 / 256, 256>>>((float*)d_out);
}